// round 2
// baseline (speedup 1.0000x reference)
#include <cuda_runtime.h>
#include <math.h>

#define B_  64
#define D_  256
#define BM  128
#define BK  32
#define INV_TEMP 20.0f
#define MOM 0.2f
#define NEG_INF (-1e30f)
#define MAX_BLK 1600

// scratch (no allocations allowed)
__device__ float g_xnT[D_ * B_];          // normalized inputs, transposed [d][b]
__device__ float g_tlogit[B_];            // logit at target per sample
__device__ float g_pmax[MAX_BLK * B_];    // per-tile softmax partials
__device__ float g_psum[MAX_BLK * B_];

__device__ __forceinline__ unsigned long long fma2(unsigned long long a,
                                                   unsigned long long b,
                                                   unsigned long long c) {
    unsigned long long d;
    asm("fma.rn.f32x2 %0, %1, %2, %3;" : "=l"(d) : "l"(a), "l"(b), "l"(c));
    return d;
}

// ---------------------------------------------------------------------------
// Kernel 1: normalize inputs (store transposed) + compute logit at target
// ---------------------------------------------------------------------------
__global__ void prep_kernel(const float* __restrict__ inp,
                            const float* __restrict__ F,
                            const int* __restrict__ tgt) {
    int tid = threadIdx.x;
    int w = tid >> 5, lane = tid & 31;
    for (int b = w; b < B_; b += 8) {
        float v[8]; float ss = 0.f;
        #pragma unroll
        for (int t = 0; t < 8; t++) {
            v[t] = inp[b * D_ + lane + 32 * t];
            ss += v[t] * v[t];
        }
        #pragma unroll
        for (int off = 16; off; off >>= 1) ss += __shfl_xor_sync(0xffffffffu, ss, off);
        float inv = 1.0f / fmaxf(sqrtf(ss), 1e-12f);
        long long t64 = (long long)tgt[b];
        float dot = 0.f;
        #pragma unroll
        for (int t = 0; t < 8; t++) {
            float xv = v[t] * inv;
            g_xnT[(lane + 32 * t) * B_ + b] = xv;
            dot += xv * F[t64 * (long long)D_ + lane + 32 * t];
        }
        #pragma unroll
        for (int off = 16; off; off >>= 1) dot += __shfl_xor_sync(0xffffffffu, dot, off);
        if (lane == 0) g_tlogit[b] = dot * INV_TEMP;
    }
}

// ---------------------------------------------------------------------------
// Kernel 2: streaming GEMM tile (128 rows x 64 cols) with f32x2 FMAs,
// fused copy features -> out, per-tile online-softmax partials.
// ---------------------------------------------------------------------------
__global__ __launch_bounds__(256, 2) void main_kernel(const float* __restrict__ F,
                                                      float* __restrict__ outF,
                                                      int N) {
    __shared__ __align__(16) float Fs[BK][BM + 2];   // transposed F tile (pad 2 keeps 8B align)
    __shared__ __align__(16) float Xd[BK][128];      // X duplicated: Xd[k][2b]=Xd[k][2b+1]=x[b][k]
    __shared__ float red[16][64];
    __shared__ float cmax[64];

    const int tid = threadIdx.x;
    const int tx = tid & 15, ty = tid >> 4;
    const int row0 = blockIdx.x * BM;

    // flat coalesced copy of this tile to output (new_features starts as features)
    {
        int rows = N - row0; if (rows > BM) rows = BM;
        const float* src = F + (size_t)row0 * D_;
        float* dst = outF + (size_t)row0 * D_;
        for (int e = tid; e < rows * D_; e += 256) dst[e] = src[e];
    }

    unsigned long long acc[4][4];
    #pragma unroll
    for (int i = 0; i < 4; i++)
        #pragma unroll
        for (int j = 0; j < 4; j++) acc[i][j] = 0ULL;

    const int lrow = tid >> 3;          // 0..31
    const int lk4  = (tid & 7) * 4;     // 0..28

    for (int k0 = 0; k0 < D_; k0 += BK) {
        // load + transpose F tile
        #pragma unroll
        for (int i = 0; i < 4; i++) {
            int r = lrow + 32 * i;
            float4 v = make_float4(0.f, 0.f, 0.f, 0.f);
            if (row0 + r < N)
                v = *reinterpret_cast<const float4*>(&F[(size_t)(row0 + r) * D_ + k0 + lk4]);
            Fs[lk4 + 0][r] = v.x;
            Fs[lk4 + 1][r] = v.y;
            Fs[lk4 + 2][r] = v.z;
            Fs[lk4 + 3][r] = v.w;
        }
        // load X slab, duplicated per element for packed-FMA broadcast
        #pragma unroll
        for (int q = 0; q < 8; q++) {
            int idx = tid + 256 * q;           // 0..2047
            int kk = idx >> 6, b = idx & 63;
            float xv = g_xnT[(k0 + kk) * B_ + b];
            float2 d2; d2.x = xv; d2.y = xv;
            *reinterpret_cast<float2*>(&Xd[kk][2 * b]) = d2;
        }
        __syncthreads();
        #pragma unroll
        for (int k = 0; k < BK; k++) {
            unsigned long long a[4], x[4];
            #pragma unroll
            for (int ip = 0; ip < 4; ip++)
                a[ip] = *reinterpret_cast<const unsigned long long*>(&Fs[k][2 * ty + 32 * ip]);
            #pragma unroll
            for (int j = 0; j < 4; j++)
                x[j] = *reinterpret_cast<const unsigned long long*>(&Xd[k][2 * (tx + 16 * j)]);
            #pragma unroll
            for (int ip = 0; ip < 4; ip++)
                #pragma unroll
                for (int j = 0; j < 4; j++)
                    acc[ip][j] = fma2(a[ip], x[j], acc[ip][j]);
        }
        __syncthreads();
    }

    // ---- per-tile softmax partials: logits = acc * 20 ----
    float mj[4] = {NEG_INF, NEG_INF, NEG_INF, NEG_INF};
    #pragma unroll
    for (int ip = 0; ip < 4; ip++) {
        int rlo = row0 + 2 * ty + 32 * ip;
        bool vlo = rlo < N, vhi = (rlo + 1) < N;
        #pragma unroll
        for (int j = 0; j < 4; j++) {
            unsigned long long v = acc[ip][j];
            float lo = __uint_as_float((unsigned)v) * INV_TEMP;
            float hi = __uint_as_float((unsigned)(v >> 32)) * INV_TEMP;
            if (vlo) mj[j] = fmaxf(mj[j], lo);
            if (vhi) mj[j] = fmaxf(mj[j], hi);
        }
    }
    #pragma unroll
    for (int j = 0; j < 4; j++) red[ty][tx + 16 * j] = mj[j];
    __syncthreads();
    if (tid < 64) {
        float m = NEG_INF;
        #pragma unroll
        for (int t = 0; t < 16; t++) m = fmaxf(m, red[t][tid]);
        cmax[tid] = m;
    }
    __syncthreads();

    float cm[4];
    #pragma unroll
    for (int j = 0; j < 4; j++) cm[j] = cmax[tx + 16 * j];
    float sj[4] = {0.f, 0.f, 0.f, 0.f};
    #pragma unroll
    for (int ip = 0; ip < 4; ip++) {
        int rlo = row0 + 2 * ty + 32 * ip;
        bool vlo = rlo < N, vhi = (rlo + 1) < N;
        #pragma unroll
        for (int j = 0; j < 4; j++) {
            unsigned long long v = acc[ip][j];
            float lo = __uint_as_float((unsigned)v) * INV_TEMP;
            float hi = __uint_as_float((unsigned)(v >> 32)) * INV_TEMP;
            if (vlo) sj[j] += __expf(lo - cm[j]);
            if (vhi) sj[j] += __expf(hi - cm[j]);
        }
    }
    #pragma unroll
    for (int j = 0; j < 4; j++) red[ty][tx + 16 * j] = sj[j];
    __syncthreads();
    if (tid < 64) {
        float s = 0.f;
        #pragma unroll
        for (int t = 0; t < 16; t++) s += red[t][tid];
        g_pmax[blockIdx.x * B_ + tid] = cmax[tid];
        g_psum[blockIdx.x * B_ + tid] = s;
    }
}

// ---------------------------------------------------------------------------
// Kernel 3: momentum scatter-update of target rows (last duplicate wins)
// ---------------------------------------------------------------------------
__global__ void scatter_kernel(const float* __restrict__ F,
                               const float* __restrict__ scores,
                               const int* __restrict__ tgt,
                               float* __restrict__ outF) {
    int b = blockIdx.x;
    int tid = threadIdx.x;
    long long t = (long long)tgt[b];
    for (int b2 = b + 1; b2 < B_; b2++)
        if (tgt[b2] == (int)t) return;   // whole block returns uniformly
    float s = scores[b];
    float u[4]; float ss = 0.f;
    #pragma unroll
    for (int q = 0; q < 4; q++) {
        int d = tid + 64 * q;
        float oldv = F[t * (long long)D_ + d];
        float xb = g_xnT[d * B_ + b];
        u[q] = MOM * oldv + (1.0f - MOM) * s * xb;
        ss += u[q] * u[q];
    }
    #pragma unroll
    for (int off = 16; off; off >>= 1) ss += __shfl_xor_sync(0xffffffffu, ss, off);
    __shared__ float sh[2];
    if ((tid & 31) == 0) sh[tid >> 5] = ss;
    __syncthreads();
    ss = sh[0] + sh[1];
    float inv = 1.0f / fmaxf(sqrtf(ss), 1e-12f);
    #pragma unroll
    for (int q = 0; q < 4; q++) {
        int d = tid + 64 * q;
        outF[t * (long long)D_ + d] = u[q] * inv;
    }
}

// ---------------------------------------------------------------------------
// Kernel 4: merge partials -> logsumexp -> weighted CE -> loss at out[0]
// ---------------------------------------------------------------------------
__global__ void finalize_kernel(const float* __restrict__ scores,
                                float* __restrict__ out, int nblk) {
    __shared__ float shm[8][64], shs[8][64], lossp[64];
    int tid = threadIdx.x;
    int b = tid & 63, sl = tid >> 6;   // 8 slices x 64 samples
    float m = NEG_INF, s = 0.f;
    for (int i = sl; i < nblk; i += 8) {
        float pm = g_pmax[i * B_ + b];
        float ps = g_psum[i * B_ + b];
        if (pm > m) { s = s * __expf(m - pm) + ps; m = pm; }
        else        { s += ps * __expf(pm - m); }
    }
    shm[sl][b] = m; shs[sl][b] = s;
    __syncthreads();
    if (tid < 64) {
        float M = NEG_INF, S = 0.f;
        #pragma unroll
        for (int q = 0; q < 8; q++) {
            float pm = shm[q][tid], ps = shs[q][tid];
            if (pm > M) { S = S * __expf(M - pm) + ps; M = pm; }
            else        { S += ps * __expf(pm - M); }
        }
        float lse = M + logf(S);
        lossp[tid] = scores[tid] * (lse - g_tlogit[tid]);
    }
    __syncthreads();
    if (tid == 0) {
        float acc = 0.f;
        for (int i = 0; i < 64; i++) acc += lossp[i];
        out[0] = acc;
    }
}

// ---------------------------------------------------------------------------
extern "C" void kernel_launch(void* const* d_in, const int* in_sizes, int n_in,
                              void* d_out, int out_size) {
    const float* inputs   = (const float*)d_in[0];
    const float* scores   = (const float*)d_in[1];
    const float* features = (const float*)d_in[2];
    const int*   targets  = (const int*)d_in[3];
    int N = in_sizes[2] / D_;
    float* out = (float*)d_out;
    float* outF = out + 1;   // out[0] = loss, out[1..] = new_features row-major
    int nblk = (N + BM - 1) / BM;

    prep_kernel<<<1, 256>>>(inputs, features, targets);
    main_kernel<<<nblk, 256>>>(features, outF, N);
    scatter_kernel<<<B_, 64>>>(features, scores, targets, outF);
    finalize_kernel<<<1, 512>>>(scores, out, nblk);
}

// round 4
// speedup vs baseline: 1.1200x; 1.1200x over previous
#include <cuda_runtime.h>
#include <math.h>

#define B_  64
#define D_  256
#define BM  128
#define BK  32
#define INV_TEMP 20.0f
#define MOM 0.2f
#define NEG_INF (-1e30f)
#define MAX_BLK 1600

// scratch (no allocations allowed)
__device__ float g_xnT[D_ * B_];            // normalized inputs, transposed [d][b]
__device__ float g_tlogit[B_];              // logit at target per sample
__device__ float g_pmax[B_ * MAX_BLK];      // per-tile softmax partials, [b][tile]
__device__ float g_psum[B_ * MAX_BLK];
__device__ float g_lse[B_];

__device__ __forceinline__ unsigned long long fma2(unsigned long long a,
                                                   unsigned long long b,
                                                   unsigned long long c) {
    unsigned long long d;
    asm("fma.rn.f32x2 %0, %1, %2, %3;" : "=l"(d) : "l"(a), "l"(b), "l"(c));
    return d;
}

// online-softmax pair merge
__device__ __forceinline__ void lse_merge(float& m, float& s, float pm, float ps) {
    if (pm > m) { s = s * __expf(m - pm) + ps; m = pm; }
    else if (pm > NEG_INF) { s += ps * __expf(pm - m); }
}

// ---------------------------------------------------------------------------
// Kernel 1: normalize inputs (store transposed) + compute logit at target
// ---------------------------------------------------------------------------
__global__ void prep_kernel(const float* __restrict__ inp,
                            const float* __restrict__ F,
                            const int* __restrict__ tgt) {
    int tid = threadIdx.x;
    int w = tid >> 5, lane = tid & 31;
    for (int b = w; b < B_; b += 8) {
        float v[8]; float ss = 0.f;
        #pragma unroll
        for (int t = 0; t < 8; t++) {
            v[t] = inp[b * D_ + lane + 32 * t];
            ss += v[t] * v[t];
        }
        #pragma unroll
        for (int off = 16; off; off >>= 1) ss += __shfl_xor_sync(0xffffffffu, ss, off);
        float inv = 1.0f / fmaxf(sqrtf(ss), 1e-12f);
        long long t64 = (long long)tgt[b];
        float dot = 0.f;
        #pragma unroll
        for (int t = 0; t < 8; t++) {
            float xv = v[t] * inv;
            g_xnT[(lane + 32 * t) * B_ + b] = xv;
            dot += xv * F[t64 * (long long)D_ + lane + 32 * t];
        }
        #pragma unroll
        for (int off = 16; off; off >>= 1) dot += __shfl_xor_sync(0xffffffffu, dot, off);
        if (lane == 0) g_tlogit[b] = dot * INV_TEMP;
    }
}

// ---------------------------------------------------------------------------
// Kernel 2: streaming GEMM tile (128 rows x 64 cols) with f32x2 FMAs.
// features->out copy FUSED into the tile load (F read exactly once from DRAM).
// outF is 4B-aligned only (out+1) -> scalar stores for the copy.
// ---------------------------------------------------------------------------
__global__ __launch_bounds__(256, 2) void main_kernel(const float* __restrict__ F,
                                                      float* __restrict__ outF,
                                                      int N) {
    __shared__ __align__(16) float Fs[BK][BM + 2];
    __shared__ __align__(16) float Xd[BK][128];     // duplicated X for packed FMA
    __shared__ float red[16][64];
    __shared__ float cmax[64];

    const int tid = threadIdx.x;
    const int tx = tid & 15, ty = tid >> 4;
    const int row0 = blockIdx.x * BM;

    unsigned long long acc[4][4];
    #pragma unroll
    for (int i = 0; i < 4; i++)
        #pragma unroll
        for (int j = 0; j < 4; j++) acc[i][j] = 0ULL;

    const int lrow = tid >> 3;          // 0..31
    const int lk4  = (tid & 7) * 4;     // 0..28

    for (int k0 = 0; k0 < D_; k0 += BK) {
        // load F tile (transposed into smem) + fused copy to outF (scalar stores)
        #pragma unroll
        for (int i = 0; i < 4; i++) {
            int r = lrow + 32 * i;
            float4 v = make_float4(0.f, 0.f, 0.f, 0.f);
            if (row0 + r < N) {
                size_t off = (size_t)(row0 + r) * D_ + k0 + lk4;
                v = *reinterpret_cast<const float4*>(&F[off]);
                outF[off + 0] = v.x;          // outF is only 4B-aligned
                outF[off + 1] = v.y;
                outF[off + 2] = v.z;
                outF[off + 3] = v.w;
            }
            Fs[lk4 + 0][r] = v.x;
            Fs[lk4 + 1][r] = v.y;
            Fs[lk4 + 2][r] = v.z;
            Fs[lk4 + 3][r] = v.w;
        }
        // load X slab, duplicated per element for packed-FMA broadcast
        #pragma unroll
        for (int q = 0; q < 8; q++) {
            int idx = tid + 256 * q;           // 0..2047
            int kk = idx >> 6, b = idx & 63;
            float xv = g_xnT[(k0 + kk) * B_ + b];
            float2 d2; d2.x = xv; d2.y = xv;
            *reinterpret_cast<float2*>(&Xd[kk][2 * b]) = d2;
        }
        __syncthreads();
        #pragma unroll
        for (int k = 0; k < BK; k++) {
            unsigned long long a[4], x[4];
            #pragma unroll
            for (int ip = 0; ip < 4; ip++)
                a[ip] = *reinterpret_cast<const unsigned long long*>(&Fs[k][2 * ty + 32 * ip]);
            #pragma unroll
            for (int j = 0; j < 4; j++)
                x[j] = *reinterpret_cast<const unsigned long long*>(&Xd[k][2 * (tx + 16 * j)]);
            #pragma unroll
            for (int ip = 0; ip < 4; ip++)
                #pragma unroll
                for (int j = 0; j < 4; j++)
                    acc[ip][j] = fma2(a[ip], x[j], acc[ip][j]);
        }
        __syncthreads();
    }

    // ---- per-tile softmax partials: logits = acc * 20 ----
    float mj[4] = {NEG_INF, NEG_INF, NEG_INF, NEG_INF};
    #pragma unroll
    for (int ip = 0; ip < 4; ip++) {
        int rlo = row0 + 2 * ty + 32 * ip;
        bool vlo = rlo < N, vhi = (rlo + 1) < N;
        #pragma unroll
        for (int j = 0; j < 4; j++) {
            unsigned long long v = acc[ip][j];
            float lo = __uint_as_float((unsigned)v) * INV_TEMP;
            float hi = __uint_as_float((unsigned)(v >> 32)) * INV_TEMP;
            if (vlo) mj[j] = fmaxf(mj[j], lo);
            if (vhi) mj[j] = fmaxf(mj[j], hi);
        }
    }
    #pragma unroll
    for (int j = 0; j < 4; j++) red[ty][tx + 16 * j] = mj[j];
    __syncthreads();
    if (tid < 64) {
        float m = NEG_INF;
        #pragma unroll
        for (int t = 0; t < 16; t++) m = fmaxf(m, red[t][tid]);
        cmax[tid] = m;
    }
    __syncthreads();

    float cm[4];
    #pragma unroll
    for (int j = 0; j < 4; j++) cm[j] = cmax[tx + 16 * j];
    float sj[4] = {0.f, 0.f, 0.f, 0.f};
    #pragma unroll
    for (int ip = 0; ip < 4; ip++) {
        int rlo = row0 + 2 * ty + 32 * ip;
        bool vlo = rlo < N, vhi = (rlo + 1) < N;
        #pragma unroll
        for (int j = 0; j < 4; j++) {
            unsigned long long v = acc[ip][j];
            float lo = __uint_as_float((unsigned)v) * INV_TEMP;
            float hi = __uint_as_float((unsigned)(v >> 32)) * INV_TEMP;
            if (vlo) sj[j] += __expf(lo - cm[j]);
            if (vhi) sj[j] += __expf(hi - cm[j]);
        }
    }
    #pragma unroll
    for (int j = 0; j < 4; j++) red[ty][tx + 16 * j] = sj[j];
    __syncthreads();
    if (tid < 64) {
        float s = 0.f;
        #pragma unroll
        for (int t = 0; t < 16; t++) s += red[t][tid];
        g_pmax[tid * MAX_BLK + blockIdx.x] = cmax[tid];   // transposed: [b][tile]
        g_psum[tid * MAX_BLK + blockIdx.x] = s;
    }
}

// ---------------------------------------------------------------------------
// Kernel 3: momentum scatter-update of target rows (last duplicate wins)
// ---------------------------------------------------------------------------
__global__ void scatter_kernel(const float* __restrict__ F,
                               const float* __restrict__ scores,
                               const int* __restrict__ tgt,
                               float* __restrict__ outF) {
    int b = blockIdx.x;
    int tid = threadIdx.x;
    int t = tgt[b];
    for (int b2 = b + 1; b2 < B_; b2++)
        if (tgt[b2] == t) return;   // whole block returns uniformly
    float s = scores[b];
    float u[4]; float ss = 0.f;
    #pragma unroll
    for (int q = 0; q < 4; q++) {
        int d = tid + 64 * q;
        float oldv = F[(long long)t * D_ + d];
        float xb = g_xnT[d * B_ + b];
        u[q] = MOM * oldv + (1.0f - MOM) * s * xb;
        ss += u[q] * u[q];
    }
    #pragma unroll
    for (int off = 16; off; off >>= 1) ss += __shfl_xor_sync(0xffffffffu, ss, off);
    __shared__ float sh[2];
    if ((tid & 31) == 0) sh[tid >> 5] = ss;
    __syncthreads();
    ss = sh[0] + sh[1];
    float inv = 1.0f / fmaxf(sqrtf(ss), 1e-12f);
    #pragma unroll
    for (int q = 0; q < 4; q++) {
        int d = tid + 64 * q;
        outF[(long long)t * D_ + d] = u[q] * inv;
    }
}

// ---------------------------------------------------------------------------
// Kernel 4a: per-sample parallel logsumexp over tile partials (64 blocks)
// ---------------------------------------------------------------------------
__global__ void lse_kernel(int nblk) {
    const int b = blockIdx.x;
    const int tid = threadIdx.x;
    float m = NEG_INF, s = 0.f;
    const float* pm = &g_pmax[b * MAX_BLK];
    const float* ps = &g_psum[b * MAX_BLK];
    for (int i = tid; i < nblk; i += 256)
        lse_merge(m, s, pm[i], ps[i]);
    // warp tree-merge
    #pragma unroll
    for (int off = 16; off; off >>= 1) {
        float m2 = __shfl_xor_sync(0xffffffffu, m, off);
        float s2 = __shfl_xor_sync(0xffffffffu, s, off);
        lse_merge(m, s, m2, s2);
    }
    __shared__ float shm[8], shs[8];
    if ((tid & 31) == 0) { shm[tid >> 5] = m; shs[tid >> 5] = s; }
    __syncthreads();
    if (tid == 0) {
        float M = shm[0], S = shs[0];
        #pragma unroll
        for (int q = 1; q < 8; q++) lse_merge(M, S, shm[q], shs[q]);
        g_lse[b] = M + logf(S);
    }
}

// ---------------------------------------------------------------------------
// Kernel 4b: weighted CE sum -> out[0]
// ---------------------------------------------------------------------------
__global__ void loss_kernel(const float* __restrict__ scores,
                            float* __restrict__ out) {
    int tid = threadIdx.x;   // 64 threads
    float v = scores[tid] * (g_lse[tid] - g_tlogit[tid]);
    #pragma unroll
    for (int off = 16; off; off >>= 1) v += __shfl_xor_sync(0xffffffffu, v, off);
    __shared__ float sh[2];
    if ((tid & 31) == 0) sh[tid >> 5] = v;
    __syncthreads();
    if (tid == 0) out[0] = sh[0] + sh[1];
}

// ---------------------------------------------------------------------------
extern "C" void kernel_launch(void* const* d_in, const int* in_sizes, int n_in,
                              void* d_out, int out_size) {
    const float* inputs   = (const float*)d_in[0];
    const float* scores   = (const float*)d_in[1];
    const float* features = (const float*)d_in[2];
    const int*   targets  = (const int*)d_in[3];
    int N = in_sizes[2] / D_;
    float* out = (float*)d_out;
    float* outF = out + 1;   // out[0] = loss, out[1..] = new_features row-major
    int nblk = (N + BM - 1) / BM;

    prep_kernel<<<1, 256>>>(inputs, features, targets);
    main_kernel<<<nblk, 256>>>(features, outF, N);
    scatter_kernel<<<B_, 64>>>(features, scores, targets, outF);
    lse_kernel<<<B_, 256>>>(nblk);
    loss_kernel<<<1, 64>>>(scores, out);
}